// round 1
// baseline (speedup 1.0000x reference)
#include <cuda_runtime.h>

#define BM 128
#define BN 128
#define BK 32
#define KD 512
#define ND 256

typedef unsigned long long u64;

__device__ __forceinline__ u64 pk2(float x) {
    u64 r;
    asm("mov.b64 %0, {%1, %1};" : "=l"(r) : "f"(x));
    return r;
}
__device__ __forceinline__ void fma2(u64& d, u64 a, u64 b) {
    asm("fma.rn.f32x2 %0, %1, %2, %3;" : "=l"(d) : "l"(a), "l"(b), "l"(d));
}
__device__ __forceinline__ float2 up2(u64 v) {
    float2 f;
    asm("mov.b64 {%0, %1}, %2;" : "=f"(f.x), "=f"(f.y) : "l"(v));
    return f;
}

__global__ void __launch_bounds__(256, 2)
linear1d_gemm_kernel(const float* __restrict__ A,   // [65536, 512]
                     const float* __restrict__ W,   // [256, 512]
                     const float* __restrict__ bias,// [256]
                     float* __restrict__ out)       // [65536, 256]
{
    __shared__ __align__(16) float As[BM][BK];   // [m][k]
    __shared__ __align__(16) float Bs[BK][BN];   // [k][n] (transposed)

    const int tid = threadIdx.x;
    const int tx  = tid & 15;      // n direction (16)
    const int ty  = tid >> 4;      // m direction (16)
    const int bm  = blockIdx.x * BM;
    const int bn  = blockIdx.y * BN;

    // global load mapping: each thread owns 4 float4 loads per tile
    const int rowL = tid >> 3;          // 0..31 base row, +32*i
    const int kc   = (tid & 7) * 4;     // k column within tile (0..28)

    const float* Aptr = A + (size_t)(bm + rowL) * KD + kc;
    const float* Wptr = W + (size_t)(bn + rowL) * KD + kc;

    u64 acc[8][4];
#pragma unroll
    for (int i = 0; i < 8; i++)
#pragma unroll
        for (int j = 0; j < 4; j++) acc[i][j] = 0ull;

    for (int kt = 0; kt < KD; kt += BK) {
        // ---- load A tile: float4 global -> float4 smem (conflict-free) ----
#pragma unroll
        for (int i = 0; i < 4; i++) {
            float4 v = *(const float4*)(Aptr + (size_t)(i * 32) * KD + kt);
            *(float4*)(&As[rowL + i * 32][kc]) = v;
        }
        // ---- load W tile: float4 global -> transposed scalar smem ----
#pragma unroll
        for (int i = 0; i < 4; i++) {
            float4 v = *(const float4*)(Wptr + (size_t)(i * 32) * KD + kt);
            int n = rowL + i * 32;
            Bs[kc + 0][n] = v.x;
            Bs[kc + 1][n] = v.y;
            Bs[kc + 2][n] = v.z;
            Bs[kc + 3][n] = v.w;
        }
        __syncthreads();

        // ---- mainloop: packed f32x2 FMAs ----
#pragma unroll
        for (int k = 0; k < BK; k++) {
            // b: consecutive float4 across lanes -> conflict-free LDS.128,
            // reinterpreted as packed f32x2 pairs (no extra mov)
            ulonglong2 b0 = *(const ulonglong2*)(&Bs[k][tx * 4]);
            ulonglong2 b1 = *(const ulonglong2*)(&Bs[k][64 + tx * 4]);
#pragma unroll
            for (int i = 0; i < 8; i++) {
                u64 a2 = pk2(As[ty * 8 + i][k]);  // warp-broadcast read
                fma2(acc[i][0], a2, b0.x);
                fma2(acc[i][1], a2, b0.y);
                fma2(acc[i][2], a2, b1.x);
                fma2(acc[i][3], a2, b1.y);
            }
        }
        __syncthreads();
    }

    // ---- epilogue: scale + 0.1*bias, vectorized coalesced stores ----
    const float scale = 0.125f;  // 1/sqrt(64)
    const float4 bv0 = *(const float4*)(bias + bn + tx * 4);
    const float4 bv1 = *(const float4*)(bias + bn + 64 + tx * 4);

#pragma unroll
    for (int i = 0; i < 8; i++) {
        const int m = bm + ty * 8 + i;
        float* orow = out + (size_t)m * ND + bn;

        float2 p0 = up2(acc[i][0]);
        float2 p1 = up2(acc[i][1]);
        float4 r0;
        r0.x = p0.x * scale + 0.1f * bv0.x;
        r0.y = p0.y * scale + 0.1f * bv0.y;
        r0.z = p1.x * scale + 0.1f * bv0.z;
        r0.w = p1.y * scale + 0.1f * bv0.w;
        *(float4*)(orow + tx * 4) = r0;

        float2 p2 = up2(acc[i][2]);
        float2 p3 = up2(acc[i][3]);
        float4 r1;
        r1.x = p2.x * scale + 0.1f * bv1.x;
        r1.y = p2.y * scale + 0.1f * bv1.y;
        r1.z = p3.x * scale + 0.1f * bv1.z;
        r1.w = p3.y * scale + 0.1f * bv1.w;
        *(float4*)(orow + 64 + tx * 4) = r1;
    }
}

extern "C" void kernel_launch(void* const* d_in, const int* in_sizes, int n_in,
                              void* d_out, int out_size) {
    const float* x      = (const float*)d_in[0];  // [65536, 512]
    const float* weight = (const float*)d_in[1];  // [256, 512]
    const float* bias   = (const float*)d_in[2];  // [256]
    float* out = (float*)d_out;                   // [65536, 256]

    dim3 grid(65536 / BM, ND / BN);   // (512, 2)
    dim3 block(256);
    linear1d_gemm_kernel<<<grid, block>>>(x, weight, bias, out);
}

// round 3
// speedup vs baseline: 2.0111x; 2.0111x over previous
#include <cuda_runtime.h>
#include <cuda_bf16.h>
#include <cstdint>

// ============================================================================
// out[65536,256] = (x[65536,512] @ W[256,512]^T) * 0.125 + 0.1*bias
// bf16 hi/lo 3-term split + mma.sync.m16n8k16 (base sm_103 — no tcgen05).
// Split kernels emit a pre-swizzled (SW64) tile-contiguous bf16 layout so the
// GEMM loads each pipeline stage with 4 cp.async.bulk ops.
// ============================================================================

#define KD 512
#define ND 256
#define MROWS 65536
#define BM 128
#define KB 32                 // k-cols per stage
#define NS 16                 // KD / KB
#define NPIPE 4
#define THREADS 512

#define A_TILE 8192           // 128 rows * 32 bf16 * 2B
#define B_TILE 16384          // 256 rows * 32 bf16 * 2B
#define STAGE_BYTES (2 * A_TILE + 2 * B_TILE)   // 49152

// ---- scratch: pre-swizzled bf16 tiles (device globals) ----
// g_xhi/g_xlo: [mblock 512][stage 16] tiles of 8KB  (64 MB each)
// g_whi/g_wlo: [stage 16] tiles of 16KB             (256 KB each)
__device__ __align__(1024) unsigned char g_xhi[(size_t)512 * 16 * A_TILE];
__device__ __align__(1024) unsigned char g_xlo[(size_t)512 * 16 * A_TILE];
__device__ __align__(1024) unsigned char g_whi[16 * B_TILE];
__device__ __align__(1024) unsigned char g_wlo[16 * B_TILE];

// SW64 swizzle: XOR bits[5:4] with bits[8:7] (atom = 8 rows x 64B = 512B)
__device__ __forceinline__ uint32_t swz64(uint32_t o) {
    return o ^ ((o >> 3) & 0x30);
}

__device__ __forceinline__ uint32_t smem_u32(const void* p) {
    uint32_t a;
    asm("{ .reg .u64 t; cvta.to.shared.u64 t, %1; cvt.u32.u64 %0, t; }"
        : "=r"(a) : "l"(p));
    return a;
}

#define MBAR_INIT(a, c) \
    asm volatile("mbarrier.init.shared.b64 [%0], %1;" :: "r"(a), "r"(c) : "memory")
#define MBAR_EXPECT_TX(a, tx) \
    asm volatile("mbarrier.arrive.expect_tx.shared.b64 _, [%0], %1;" \
                 :: "r"(a), "r"(tx) : "memory")
#define MBAR_ARRIVE(a) \
    asm volatile("mbarrier.arrive.shared.b64 _, [%0];" :: "r"(a) : "memory")
#define MBAR_WAIT(a, par) do {                                              \
    asm volatile(                                                           \
        "{\n\t.reg .pred P1;\n\t"                                           \
        "WL_%=:\n\t"                                                        \
        "mbarrier.try_wait.parity.acquire.cta.shared::cta.b64 P1, [%0], %1, 0x989680;\n\t" \
        "@P1 bra.uni WD_%=;\n\t"                                            \
        "bra.uni WL_%=;\n\t"                                                \
        "WD_%=:\n\t}"                                                       \
        :: "r"(a), "r"(par) : "memory");                                    \
} while (0)

#define BULK_G2S(dst, src, sz, mbar) \
    asm volatile("cp.async.bulk.shared::cta.global.mbarrier::complete_tx::bytes " \
                 "[%0], [%1], %2, [%3];" \
                 :: "r"(dst), "l"(src), "r"(sz), "r"(mbar) : "memory")

#define LDSM4(r, addr) \
    asm volatile("ldmatrix.sync.aligned.m8n8.x4.shared.b16 {%0,%1,%2,%3}, [%4];" \
                 : "=r"((r)[0]), "=r"((r)[1]), "=r"((r)[2]), "=r"((r)[3])  \
                 : "r"(addr))

#define MMA(d, a, b0, b1) \
    asm volatile("mma.sync.aligned.m16n8k16.row.col.f32.bf16.bf16.f32 " \
                 "{%0,%1,%2,%3}, {%4,%5,%6,%7}, {%8,%9}, {%0,%1,%2,%3};" \
                 : "+f"((d)[0]), "+f"((d)[1]), "+f"((d)[2]), "+f"((d)[3]) \
                 : "r"((a)[0]), "r"((a)[1]), "r"((a)[2]), "r"((a)[3]),    \
                   "r"(b0), "r"(b1))

// ============================================================================
// Split kernels: fp32 -> bf16 hi/lo in pre-swizzled tile layout.
// Element (r, k): stage s=k/32, tile (block, s), in-tile offset
//   swz64((r%rows)*64 + ((k%32)/8)*16) + ((k%8)/4)*8
// Each thread handles one float4 -> one 8B store per buffer.
// ============================================================================
__global__ void split_x_kernel(const float* __restrict__ src) {
    const int n4 = MROWS * KD / 4;                    // 8388608
    int i = blockIdx.x * blockDim.x + threadIdx.x;
    const int stride = gridDim.x * blockDim.x;
    for (; i < n4; i += stride) {
        float4 v = ((const float4*)src)[i];
        int r = i >> 7;                 // row (128 float4 per row)
        int c4 = i & 127;
        int s = c4 >> 3;                // k-stage
        int cc = c4 & 7;                // float4 within stage (8 per stage)
        int c16 = cc >> 1;              // 16B chunk
        int sub8 = (cc & 1) * 8;
        int b = r >> 7;
        int rr = r & 127;
        size_t tile = ((size_t)(b * 16 + s)) * A_TILE;
        uint32_t off = swz64((uint32_t)(rr * 64 + c16 * 16)) + sub8;

        __nv_bfloat16 h0 = __float2bfloat16_rn(v.x);
        __nv_bfloat16 h1 = __float2bfloat16_rn(v.y);
        __nv_bfloat16 h2 = __float2bfloat16_rn(v.z);
        __nv_bfloat16 h3 = __float2bfloat16_rn(v.w);
        __nv_bfloat162 hp0(h0, h1), hp1(h2, h3);
        __nv_bfloat162 lp0(__float2bfloat16_rn(v.x - __bfloat162float(h0)),
                           __float2bfloat16_rn(v.y - __bfloat162float(h1)));
        __nv_bfloat162 lp1(__float2bfloat16_rn(v.z - __bfloat162float(h2)),
                           __float2bfloat16_rn(v.w - __bfloat162float(h3)));
        uint2 hv = make_uint2(*(uint32_t*)&hp0, *(uint32_t*)&hp1);
        uint2 lv = make_uint2(*(uint32_t*)&lp0, *(uint32_t*)&lp1);
        *(uint2*)(g_xhi + tile + off) = hv;
        *(uint2*)(g_xlo + tile + off) = lv;
    }
}

__global__ void split_w_kernel(const float* __restrict__ src) {
    const int n4 = ND * KD / 4;                       // 32768
    int i = blockIdx.x * blockDim.x + threadIdx.x;
    if (i >= n4) return;
    float4 v = ((const float4*)src)[i];
    int r = i >> 7;
    int c4 = i & 127;
    int s = c4 >> 3;
    int cc = c4 & 7;
    int c16 = cc >> 1;
    int sub8 = (cc & 1) * 8;
    size_t tile = (size_t)s * B_TILE;
    uint32_t off = swz64((uint32_t)(r * 64 + c16 * 16)) + sub8;

    __nv_bfloat16 h0 = __float2bfloat16_rn(v.x);
    __nv_bfloat16 h1 = __float2bfloat16_rn(v.y);
    __nv_bfloat16 h2 = __float2bfloat16_rn(v.z);
    __nv_bfloat16 h3 = __float2bfloat16_rn(v.w);
    __nv_bfloat162 hp0(h0, h1), hp1(h2, h3);
    __nv_bfloat162 lp0(__float2bfloat16_rn(v.x - __bfloat162float(h0)),
                       __float2bfloat16_rn(v.y - __bfloat162float(h1)));
    __nv_bfloat162 lp1(__float2bfloat16_rn(v.z - __bfloat162float(h2)),
                       __float2bfloat16_rn(v.w - __bfloat162float(h3)));
    *(uint2*)(g_whi + tile + off) = make_uint2(*(uint32_t*)&hp0, *(uint32_t*)&hp1);
    *(uint2*)(g_wlo + tile + off) = make_uint2(*(uint32_t*)&lp0, *(uint32_t*)&lp1);
}

// ============================================================================
// GEMM kernel
// smem: [0..31] full mbar x4, [32..63] empty mbar x4, [1024+] 4 stage buffers
// stage buffer: AHI(8K) ALO(8K) BHI(16K) BLO(16K)
// ============================================================================
#define SMEM_TOTAL (1024 + NPIPE * STAGE_BYTES)

__global__ void __launch_bounds__(THREADS)
gemm_hmma_kernel(const float* __restrict__ bias, float* __restrict__ out) {
    extern __shared__ __align__(1024) char smem[];
    const uint32_t sb = smem_u32(smem);
    const int tid = threadIdx.x;
    const int wid = tid >> 5;
    const int lane = tid & 31;
    const int wm = wid & 3;          // warp m index (0..3), tile rows wm*32
    const int wn = wid >> 2;         // warp n index (0..3), tile cols wn*64
    const int bIdx = blockIdx.x;
    const int bm = bIdx * BM;

    if (tid == 0) {
#pragma unroll
        for (int j = 0; j < NPIPE; j++) {
            MBAR_INIT(sb + j * 8, 1);            // full: tx-based
            MBAR_INIT(sb + 32 + j * 8, 16);      // empty: 16 warps
        }
        asm volatile("fence.proxy.async.shared::cta;" ::: "memory");
    }
    __syncthreads();

    // prologue: issue stages 0..NPIPE-2
    if (tid == 0) {
#pragma unroll
        for (int t = 0; t < NPIPE - 1; t++) {
            const uint32_t buf = sb + 1024 + t * STAGE_BYTES;
            const uint32_t mb = sb + t * 8;
            MBAR_EXPECT_TX(mb, (uint32_t)STAGE_BYTES);
            BULK_G2S(buf,         g_xhi + ((size_t)(bIdx * 16 + t)) * A_TILE, A_TILE, mb);
            BULK_G2S(buf + 8192,  g_xlo + ((size_t)(bIdx * 16 + t)) * A_TILE, A_TILE, mb);
            BULK_G2S(buf + 16384, g_whi + (size_t)t * B_TILE, B_TILE, mb);
            BULK_G2S(buf + 32768, g_wlo + (size_t)t * B_TILE, B_TILE, mb);
        }
    }

    // per-lane ldmatrix offset precompute
    const int lrow8 = ((lane >> 3) & 1) * 8 + (lane & 7);
    const int lk16 = (lane >> 4) * 16;
    uint32_t aoff[2], boff[4];
#pragma unroll
    for (int mi = 0; mi < 2; mi++)
        aoff[mi] = (uint32_t)((wm * 32 + mi * 16 + lrow8) * 64 + lk16);
#pragma unroll
    for (int g = 0; g < 4; g++)
        boff[g] = (uint32_t)((wn * 64 + g * 16 + lrow8) * 64 + lk16);

    float acc[2][8][4];
#pragma unroll
    for (int mi = 0; mi < 2; mi++)
#pragma unroll
        for (int ni = 0; ni < 8; ni++)
#pragma unroll
            for (int j = 0; j < 4; j++) acc[mi][ni][j] = 0.0f;

#pragma unroll 1
    for (int s = 0; s < NS; s++) {
        // producer: issue stage s + NPIPE - 1
        if (tid == 0) {
            const int t = s + NPIPE - 1;
            if (t < NS) {
                const int j = t & (NPIPE - 1);
                if (t >= NPIPE) {
                    MBAR_WAIT(sb + 32 + j * 8, (uint32_t)(((t >> 2) - 1) & 1));
                }
                const uint32_t buf = sb + 1024 + j * STAGE_BYTES;
                const uint32_t mb = sb + j * 8;
                MBAR_EXPECT_TX(mb, (uint32_t)STAGE_BYTES);
                BULK_G2S(buf,         g_xhi + ((size_t)(bIdx * 16 + t)) * A_TILE, A_TILE, mb);
                BULK_G2S(buf + 8192,  g_xlo + ((size_t)(bIdx * 16 + t)) * A_TILE, A_TILE, mb);
                BULK_G2S(buf + 16384, g_whi + (size_t)t * B_TILE, B_TILE, mb);
                BULK_G2S(buf + 32768, g_wlo + (size_t)t * B_TILE, B_TILE, mb);
            }
        }

        const int j = s & (NPIPE - 1);
        MBAR_WAIT(sb + j * 8, (uint32_t)((s >> 2) & 1));

        const uint32_t buf = sb + 1024 + j * STAGE_BYTES;
        const uint32_t ahi = buf, alo = buf + 8192;
        const uint32_t bhi = buf + 16384, blo = buf + 32768;

#pragma unroll
        for (int ks = 0; ks < 2; ks++) {
            const uint32_t kadd = ks * 32;
            uint32_t ah[2][4], bht[4][4];
#pragma unroll
            for (int mi = 0; mi < 2; mi++) LDSM4(ah[mi], ahi + swz64(aoff[mi] + kadd));
#pragma unroll
            for (int g = 0; g < 4; g++)    LDSM4(bht[g], bhi + swz64(boff[g] + kadd));
            // hi * hi
#pragma unroll
            for (int mi = 0; mi < 2; mi++)
#pragma unroll
                for (int g = 0; g < 4; g++) {
                    MMA(acc[mi][2 * g],     ah[mi], bht[g][0], bht[g][2]);
                    MMA(acc[mi][2 * g + 1], ah[mi], bht[g][1], bht[g][3]);
                }
            // hi * lo
            {
                uint32_t blt[4][4];
#pragma unroll
                for (int g = 0; g < 4; g++) LDSM4(blt[g], blo + swz64(boff[g] + kadd));
#pragma unroll
                for (int mi = 0; mi < 2; mi++)
#pragma unroll
                    for (int g = 0; g < 4; g++) {
                        MMA(acc[mi][2 * g],     ah[mi], blt[g][0], blt[g][2]);
                        MMA(acc[mi][2 * g + 1], ah[mi], blt[g][1], blt[g][3]);
                    }
            }
            // lo * hi
            {
                uint32_t al[2][4];
#pragma unroll
                for (int mi = 0; mi < 2; mi++) LDSM4(al[mi], alo + swz64(aoff[mi] + kadd));
#pragma unroll
                for (int mi = 0; mi < 2; mi++)
#pragma unroll
                    for (int g = 0; g < 4; g++) {
                        MMA(acc[mi][2 * g],     al[mi], bht[g][0], bht[g][2]);
                        MMA(acc[mi][2 * g + 1], al[mi], bht[g][1], bht[g][3]);
                    }
            }
        }

        if (lane == 0) MBAR_ARRIVE(sb + 32 + j * 8);
    }

    // ---- epilogue ----
    const int quad = lane >> 2;
    const int tq = lane & 3;
    const float scale = 0.125f;
#pragma unroll
    for (int mi = 0; mi < 2; mi++) {
        const int row0 = bm + wm * 32 + mi * 16 + quad;
#pragma unroll
        for (int ni = 0; ni < 8; ni++) {
            const int col = wn * 64 + ni * 8 + tq * 2;
            const float2 bv = *(const float2*)(bias + col);
            float2 o0, o1;
            o0.x = acc[mi][ni][0] * scale + 0.1f * bv.x;
            o0.y = acc[mi][ni][1] * scale + 0.1f * bv.y;
            o1.x = acc[mi][ni][2] * scale + 0.1f * bv.x;
            o1.y = acc[mi][ni][3] * scale + 0.1f * bv.y;
            *(float2*)(out + (size_t)row0 * ND + col) = o0;
            *(float2*)(out + (size_t)(row0 + 8) * ND + col) = o1;
        }
    }
}

// ============================================================================
extern "C" void kernel_launch(void* const* d_in, const int* in_sizes, int n_in,
                              void* d_out, int out_size) {
    const float* x      = (const float*)d_in[0];   // [65536, 512]
    const float* weight = (const float*)d_in[1];   // [256, 512]
    const float* bias   = (const float*)d_in[2];   // [256]
    float* out = (float*)d_out;                    // [65536, 256]

    cudaFuncSetAttribute(gemm_hmma_kernel,
                         cudaFuncAttributeMaxDynamicSharedMemorySize, SMEM_TOTAL);

    split_x_kernel<<<8192, 256>>>(x);
    split_w_kernel<<<128, 256>>>(weight);
    gemm_hmma_kernel<<<MROWS / BM, THREADS, SMEM_TOTAL>>>(bias, out);
}